// round 11
// baseline (speedup 1.0000x reference)
#include <cuda_runtime.h>
#include <math.h>

// PennyLaneBasicDQN: 16-qubit VQC (RY embed + 4x[Rot,CZ chain]) + linear head.
// Heisenberg light-cone + Pauli-transfer-matrix method (verified R3..R10).
// R11: (a) dense closed-form t64 build (init has 4 nonzeros -> no shuffle
// stages), (b) slim register-only elect FC tail, (c) contraction vector prep
// hoisted before the build barrier.

#define NQ 16
#define NA 6
#define BATCHSZ 512
#define NCHUNK 8
#define SPC 64
#define APAD 264          // padded p0-slice stride (floats)

__device__ __align__(16) float g_z[BATCHSZ * NQ];
__device__ int   g_cnt[NCHUNK] = {0};

struct C2 { float x, y; };
__device__ __forceinline__ C2 cmk(float a, float b){ C2 r; r.x=a; r.y=b; return r; }
__device__ __forceinline__ C2 cml(C2 a, C2 b){ return cmk(a.x*b.x - a.y*b.y, a.x*b.y + a.y*b.x); }
__device__ __forceinline__ C2 cad(C2 a, C2 b){ return cmk(a.x+b.x, a.y+b.y); }

// Column p of the 4x4 real PTM of conjugation O -> U^dag O U
__device__ __forceinline__ void ptm_col(const C2 u[4], int p, float col[4]) {
    C2 ud00 = cmk(u[0].x, -u[0].y), ud01 = cmk(u[2].x, -u[2].y);
    C2 ud10 = cmk(u[1].x, -u[1].y), ud11 = cmk(u[3].x, -u[3].y);
    C2 s00, s01, s10, s11;                 // sigma_p * U
    if (p == 0)      { s00=u[0]; s01=u[1]; s10=u[2]; s11=u[3]; }
    else if (p == 1) { s00=u[2]; s01=u[3]; s10=u[0]; s11=u[1]; }
    else if (p == 2) {
        s00 = cmk( u[2].y, -u[2].x);
        s01 = cmk( u[3].y, -u[3].x);
        s10 = cmk(-u[0].y,  u[0].x);
        s11 = cmk(-u[1].y,  u[1].x);
    } else           { s00=u[0]; s01=u[1]; s10=cmk(-u[2].x,-u[2].y); s11=cmk(-u[3].x,-u[3].y); }
    C2 A00 = cad(cml(ud00, s00), cml(ud01, s10));
    C2 A01 = cad(cml(ud00, s01), cml(ud01, s11));
    C2 A10 = cad(cml(ud10, s00), cml(ud11, s10));
    C2 A11 = cad(cml(ud10, s01), cml(ud11, s11));
    col[0] = 0.5f*(A00.x + A11.x);
    col[1] = 0.5f*(A01.x + A10.x);
    col[2] = 0.5f*(A10.y - A01.y);
    col[3] = 0.5f*(A00.x - A11.x);
}

// PennyLane Rot(phi,theta,omega) = RZ(omega) RY(theta) RZ(phi)
__device__ __forceinline__ void rot_u(const float* wp, C2 u[4]) {
    float phi = wp[0], th = wp[1], om = wp[2];
    float c, s; __sincosf(0.5f*th, &s, &c);
    float epx, epy, emx, emy;
    __sincosf(-0.5f*(phi+om), &epy, &epx);
    __sincosf(-0.5f*(phi-om), &emy, &emx);
    u[0] = cmk( epx*c,  epy*c);
    u[1] = cmk(-emx*s,  emy*s);
    u[2] = cmk( emx*s,  emy*s);
    u[3] = cmk( epx*c, -epy*c);
}

__global__ __launch_bounds__(256)
void vqc_fused(const float* __restrict__ x, const float* __restrict__ W,
               const float* __restrict__ fcw, const float* __restrict__ fcb,
               float* __restrict__ out)
{
    __shared__ float PT[15][16];          // conj-PTMs: layers 1..3 x window pos 0..4
    __shared__ float bx[7][3], bz[7][3];  // layer-0 Bloch columns, wires i-3..i+3
    __shared__ float sC[256];             // compact tensor [b0*4+q1][lane=(q2,q3,b4)]
    __shared__ __align__(16) float tF[4 * APAD];
    __shared__ int s_elect;

    const int i     = blockIdx.x;         // measured qubit
    const int chunk = blockIdx.y;         // 64-sample chunk
    const int tid   = threadIdx.x;
    const int lane  = tid & 31;
    const int wrp   = tid >> 5;
    const int sl    = tid >> 2;           // local sample 0..63
    const int as    = tid & 3;            // p0 slice in contraction
    const int b     = chunk * SPC + sl;

    // issue x loads early (hidden behind prologue)
    float xv[7];
    #pragma unroll
    for (int k = 0; k < 7; k++) {
        int w = i - 3 + k;
        xv[k] = (w >= 0 && w < NQ) ? x[b*NQ + w] : 0.f;
    }

    // ---- prologue: column-parallel PTM + Bloch construction ----
    if (tid < 60) {
        int id = tid >> 2, p = tid & 3;
        int l = 1 + id / 5, a = id % 5;
        int w = i - 2 + a;
        float col[4];
        if (w >= 0 && w < NQ) {
            C2 u[4]; rot_u(W + (l*NQ + w)*3, u);
            ptm_col(u, p, col);
        } else {
            #pragma unroll
            for (int q = 0; q < 4; q++) col[q] = (q == p) ? 1.f : 0.f;
        }
        #pragma unroll
        for (int q = 0; q < 4; q++) PT[id][q*4 + p] = col[q];
    } else if (tid >= 64 && tid < 78) {
        int id = tid - 64;
        int k = id >> 1;
        int p = (id & 1) ? 3 : 1;
        int w = i - 3 + k;
        float col[4] = {0.f, 0.f, 0.f, 0.f};
        if (w >= 0 && w < NQ) {
            C2 u[4]; rot_u(W + w*3, u);
            C2 v[4] = { cmk(u[0].x,-u[0].y), cmk(u[2].x,-u[2].y),
                        cmk(u[1].x,-u[1].y), cmk(u[3].x,-u[3].y) };
            ptm_col(v, p, col);
        }
        float* dstv = (p == 1) ? bx[k] : bz[k];
        dstv[0] = col[1]; dstv[1] = col[2]; dstv[2] = col[3];
    }
    __syncthreads();                      // B1

    const int q2 = (lane >> 3) & 3, q3 = (lane >> 1) & 3, b4 = lane & 1;

    // ---- warp 0 ONLY: build -> compact sC ----
    if (wrp == 0) {
        const int ex1 = (i >= 1), ex2 = (i <= 14);
        const int zx1 = ex1 ? 3 : 0, zx2 = ex2 ? 3 : 0;
        const float cI = PT[12][3], cX = PT[12][7], cY = PT[12][11], cZ = PT[12][15];

        // Dense closed-form t64 (init has 4 nonzeros):
        // t64[q1,q2,q3] = M6[q1,0]*M8[q3,0]*(cI*M7[q2,0]+cZ*M7[q2,3])
        //               + M6[q1,zx1]*M8[q3,zx2]*(cX*M7[q2,1]+cY*M7[q2,2])
        const float* M6 = PT[6]; const float* M7 = PT[7]; const float* M8 = PT[8];
        float v0, v1;   // lane holds f=lane (v0), f=32+lane (v1); f = q1*16+q2*4+q3
        {
            int f0 = lane;
            int a1 = f0 >> 4, a2 = (f0 >> 2) & 3, a3 = f0 & 3;   // v1: a1+2
            float tIZ = cI*M7[a2*4+0] + cZ*M7[a2*4+3];
            float tXY = cX*M7[a2*4+1] + cY*M7[a2*4+2];
            float e80 = M8[a3*4+0], e8z = M8[a3*4+zx2];
            v0 = M6[a1*4+0]*e80*tIZ     + M6[a1*4+zx1]*e8z*tXY;
            v1 = M6[(a1+2)*4+0]*e80*tIZ + M6[(a1+2)*4+zx1]*e8z*tXY;
        }

        // D1 as a register GATHER (CZ label map is an involution)
        const int exA0 = (i >= 2), exA1 = (i >= 1), exA2 = (i <= 14), exA3 = (i <= 13);
        float Cg[8];
        {
            const bool need4 = (exA3 && ((q3 == 1) || (q3 == 2)));
            const bool ok4 = (b4 == (need4 ? 1 : 0));
            #pragma unroll
            for (int j = 0; j < 4; j++) {
                int p1 = j, p2 = q2, p3 = q3; float s = 1.f;
                if (exA1) {
                    bool xl = (p1==1)||(p1==2), xr = (p2==1)||(p2==2);
                    if (xl && xr && p1 != p2) s = -s;
                    int np1 = xr ? p1^3 : p1, np2 = xl ? p2^3 : p2;
                    p1 = np1; p2 = np2;
                }
                if (exA2) {
                    bool xl = (p2==1)||(p2==2), xr = (p3==1)||(p3==2);
                    if (xl && xr && p2 != p3) s = -s;
                    int np2 = xr ? p2^3 : p2, np3 = xl ? p3^3 : p3;
                    p2 = np2; p3 = np3;
                }
                int fsrc = p1*16 + p2*4 + p3;
                float a0 = __shfl_sync(0xffffffffu, v0, fsrc & 31);
                float a1 = __shfl_sync(0xffffffffu, v1, fsrc & 31);
                float val = s * ((fsrc & 32) ? a1 : a0);
                bool need0 = (exA0 && ((p1 == 1) || (p1 == 2)));
                Cg[j]     = (ok4 && !need0) ? val : 0.f;
                Cg[j + 4] = (ok4 &&  need0) ? val : 0.f;
            }
        }
        {   // layer-1 axis q1 (PT[1]) : register 4x4 within each b0 group
            const float* M = PT[1];
            float N[8];
            #pragma unroll
            for (int g0 = 0; g0 < 2; g0++)
                #pragma unroll
                for (int q = 0; q < 4; q++)
                    N[g0*4+q] = M[q*4+0]*Cg[g0*4+0] + M[q*4+1]*Cg[g0*4+1]
                              + M[q*4+2]*Cg[g0*4+2] + M[q*4+3]*Cg[g0*4+3];
            #pragma unroll
            for (int k = 0; k < 8; k++) Cg[k] = N[k];
        }
        {   // layer-1 axis q2 (PT[2]) : shfl_xor 8,16,24
            const float* M = PT[2];
            float n[8];
            #pragma unroll
            for (int k = 0; k < 8; k++) {
                float s1 = __shfl_xor_sync(0xffffffffu, Cg[k], 8);
                float s2 = __shfl_xor_sync(0xffffffffu, Cg[k], 16);
                float s3 = __shfl_xor_sync(0xffffffffu, Cg[k], 24);
                n[k] = M[q2*4+q2]*Cg[k] + M[q2*4+(q2^1)]*s1
                     + M[q2*4+(q2^2)]*s2 + M[q2*4+(q2^3)]*s3;
            }
            #pragma unroll
            for (int k = 0; k < 8; k++) Cg[k] = n[k];
        }
        {   // layer-1 axis q3 (PT[3]) : shfl_xor 2,4,6
            const float* M = PT[3];
            float n[8];
            #pragma unroll
            for (int k = 0; k < 8; k++) {
                float s1 = __shfl_xor_sync(0xffffffffu, Cg[k], 2);
                float s2 = __shfl_xor_sync(0xffffffffu, Cg[k], 4);
                float s3 = __shfl_xor_sync(0xffffffffu, Cg[k], 6);
                n[k] = M[q3*4+q3]*Cg[k] + M[q3*4+(q3^1)]*s1
                     + M[q3*4+(q3^2)]*s2 + M[q3*4+(q3^3)]*s3;
            }
            #pragma unroll
            for (int k = 0; k < 8; k++) Cg[k] = n[k];
        }
        #pragma unroll
        for (int k = 0; k < 8; k++) sC[k*32 + lane] = Cg[k];
    }

    // per-sample Bloch vectors + contraction vector prep (warps 1-7 overlap
    // this with warp 0's build)
    float m[7][3];
    #pragma unroll
    for (int k = 0; k < 7; k++) {
        float sx, cx; __sincosf(xv[k], &sx, &cx);
        m[k][0] = sx*bx[k][0] + cx*bz[k][0];
        m[k][1] = sx*bx[k][1] + cx*bz[k][1];
        m[k][2] = sx*bx[k][2] + cx*bz[k][2];
    }
    float dL = (i - 3 >= 0) ? m[0][2] : 1.f;
    float dR = (i + 3 < NQ) ? m[6][2] : 1.f;
    float v0c[4], v1c[4], v2c[4], v3c[4], v4c[4];
    v0c[0]=1.f; v0c[1]=dL*m[1][0]; v0c[2]=dL*m[1][1]; v0c[3]=m[1][2];
    v1c[0]=1.f; v1c[1]=m[2][0];    v1c[2]=m[2][1];    v1c[3]=m[2][2];
    v2c[0]=1.f; v2c[1]=m[3][0];    v2c[2]=m[3][1];    v2c[3]=m[3][2];
    v3c[0]=1.f; v3c[1]=m[4][0];    v3c[2]=m[4][1];    v3c[3]=m[4][2];
    v4c[0]=1.f; v4c[1]=dR*m[5][0]; v4c[2]=dR*m[5][1]; v4c[3]=m[5][2];
    __syncthreads();                      // B2: sC published

    // ---- edge expansion (PTM cols I,Z) + D0 CZ scatter; all 8 warps:
    //      warp -> p0 = wrp>>1, p4 pair = wrp&1; lane parity -> p4 low bit.
    {
        const int p0 = wrp >> 1;
        const float c00 = PT[0][p0*4], c0z = PT[0][p0*4+3];
        const int p4 = ((wrp & 1) << 1) | b4;
        const float* M4 = PT[4];
        const int le = lane & ~1, lo = lane | 1;
        #pragma unroll
        for (int r = 0; r < 4; r++) {
            float h0 = c00 * sC[r*32 + le] + c0z * sC[(4+r)*32 + le];  // b4=0
            float h1 = c00 * sC[r*32 + lo] + c0z * sC[(4+r)*32 + lo];  // b4=1
            float sg = M4[p4*4+0]*h0 + M4[p4*4+3]*h1;
            int p[5] = { p0, r, q2, q3, p4 };
            #pragma unroll
            for (int a = 0; a < 4; a++) {
                int wl = i - 2 + a;
                if (wl >= 0 && wl + 1 < NQ) {
                    int pa = p[a], pb = p[a+1];
                    bool xl = (pa==1)||(pa==2), xr = (pb==1)||(pb==2);
                    if (xl && xr && pa != pb) sg = -sg;
                    if (xr) p[a]   = pa ^ 3;
                    if (xl) p[a+1] = pb ^ 3;
                }
            }
            tF[p[0]*APAD + (p[1]<<6) + (p[2]<<4) + (p[3]<<2) + p[4]] = sg;
        }
    }
    __syncthreads();                      // B3

    // ---- per-sample contraction: 4 threads/sample (p0 slice = as) ----
    const float4* Ta = reinterpret_cast<const float4*>(tF + as * APAD);
    float sb[4];
    #pragma unroll
    for (int q = 0; q < 4; q++) {
        float acc = 0.f;
        #pragma unroll
        for (int c = 0; c < 4; c++) {
            float sc = 0.f;
            #pragma unroll
            for (int d = 0; d < 4; d++) {
                float4 t4 = Ta[q*16 + c*4 + d];
                sc += v3c[d] * (t4.x*v4c[0] + t4.y*v4c[1] + t4.z*v4c[2] + t4.w*v4c[3]);
            }
            acc += v2c[c] * sc;
        }
        sb[q] = acc;
    }
    float z = v0c[as] * (v1c[0]*sb[0] + v1c[1]*sb[1] + v1c[2]*sb[2] + v1c[3]*sb[3]);
    z += __shfl_xor_sync(0xffffffffu, z, 1);
    z += __shfl_xor_sync(0xffffffffu, z, 2);
    if (as == 0) g_z[b * NQ + i] = z;

    // ---- fused FC head: last CTA of this chunk, register-only GEMV ----
    __syncthreads();                      // B4
    if (tid == 0) {
        __threadfence();
        int old = atomicAdd(&g_cnt[chunk], 1);
        int e = (old == NQ - 1);
        if (e) {
            __threadfence();
            atomicExch(&g_cnt[chunk], 0);   // reset for next graph replay
        }
        s_elect = e;
    }
    __syncthreads();                      // B5
    if (s_elect) {
        // thread -> (sample sl, quarter as); one float4 of z per thread
        const float4 zz = __ldcg(reinterpret_cast<const float4*>(
                              g_z + (chunk * SPC + sl) * NQ) + as);
        float pa[NA];
        #pragma unroll
        for (int a = 0; a < NA; a++) {
            const float4 wv = *reinterpret_cast<const float4*>(fcw + a*NQ + as*4);
            pa[a] = zz.x*wv.x + zz.y*wv.y + zz.z*wv.z + zz.w*wv.w;
        }
        #pragma unroll
        for (int a = 0; a < NA; a++) {
            pa[a] += __shfl_xor_sync(0xffffffffu, pa[a], 1);
            pa[a] += __shfl_xor_sync(0xffffffffu, pa[a], 2);
        }
        if (as == 0) {
            #pragma unroll
            for (int a = 0; a < NA; a++)
                out[(chunk * SPC + sl) * NA + a] = pa[a] + fcb[a];
        }
    }
}

extern "C" void kernel_launch(void* const* d_in, const int* in_sizes, int n_in,
                              void* d_out, int out_size) {
    const float* x   = (const float*)d_in[0];   // [512,16]
    const float* W   = (const float*)d_in[1];   // [4,16,3]
    const float* fcw = (const float*)d_in[2];   // [6,16]
    const float* fcb = (const float*)d_in[3];   // [6]
    float* out = (float*)d_out;                 // [512,6]
    (void)in_sizes; (void)n_in; (void)out_size;
    dim3 grid(NQ, NCHUNK);
    vqc_fused<<<grid, 256>>>(x, W, fcw, fcb, out);
}

// round 12
// speedup vs baseline: 1.0841x; 1.0841x over previous
#include <cuda_runtime.h>
#include <math.h>

// PennyLaneBasicDQN: 16-qubit VQC (RY embed + 4x[Rot,CZ chain]) + linear head.
// Heisenberg light-cone + Pauli-transfer-matrix method (verified R3..R11).
// R12: Bloch-vector deduplication — warps 1-7 compute each distinct
// (sample, wire) sincos ONCE into smem (was 4x redundant per quad =>
// ~3584 MUFU/CTA, ~half the kernel cycles), overlapped with warp 0's build.

#define NQ 16
#define NA 6
#define BATCHSZ 512
#define NCHUNK 8
#define SPC 64
#define APAD 264          // padded p0-slice stride (floats)
#define MST 22            // sM row stride (floats)

__device__ __align__(16) float g_z[BATCHSZ * NQ];
__device__ int   g_cnt[NCHUNK] = {0};

struct C2 { float x, y; };
__device__ __forceinline__ C2 cmk(float a, float b){ C2 r; r.x=a; r.y=b; return r; }
__device__ __forceinline__ C2 cml(C2 a, C2 b){ return cmk(a.x*b.x - a.y*b.y, a.x*b.y + a.y*b.x); }
__device__ __forceinline__ C2 cad(C2 a, C2 b){ return cmk(a.x+b.x, a.y+b.y); }

// Column p of the 4x4 real PTM of conjugation O -> U^dag O U
__device__ __forceinline__ void ptm_col(const C2 u[4], int p, float col[4]) {
    C2 ud00 = cmk(u[0].x, -u[0].y), ud01 = cmk(u[2].x, -u[2].y);
    C2 ud10 = cmk(u[1].x, -u[1].y), ud11 = cmk(u[3].x, -u[3].y);
    C2 s00, s01, s10, s11;                 // sigma_p * U
    if (p == 0)      { s00=u[0]; s01=u[1]; s10=u[2]; s11=u[3]; }
    else if (p == 1) { s00=u[2]; s01=u[3]; s10=u[0]; s11=u[1]; }
    else if (p == 2) {
        s00 = cmk( u[2].y, -u[2].x);
        s01 = cmk( u[3].y, -u[3].x);
        s10 = cmk(-u[0].y,  u[0].x);
        s11 = cmk(-u[1].y,  u[1].x);
    } else           { s00=u[0]; s01=u[1]; s10=cmk(-u[2].x,-u[2].y); s11=cmk(-u[3].x,-u[3].y); }
    C2 A00 = cad(cml(ud00, s00), cml(ud01, s10));
    C2 A01 = cad(cml(ud00, s01), cml(ud01, s11));
    C2 A10 = cad(cml(ud10, s00), cml(ud11, s10));
    C2 A11 = cad(cml(ud10, s01), cml(ud11, s11));
    col[0] = 0.5f*(A00.x + A11.x);
    col[1] = 0.5f*(A01.x + A10.x);
    col[2] = 0.5f*(A10.y - A01.y);
    col[3] = 0.5f*(A00.x - A11.x);
}

// PennyLane Rot(phi,theta,omega) = RZ(omega) RY(theta) RZ(phi)
__device__ __forceinline__ void rot_u(const float* wp, C2 u[4]) {
    float phi = wp[0], th = wp[1], om = wp[2];
    float c, s; __sincosf(0.5f*th, &s, &c);
    float epx, epy, emx, emy;
    __sincosf(-0.5f*(phi+om), &epy, &epx);
    __sincosf(-0.5f*(phi-om), &emy, &emx);
    u[0] = cmk( epx*c,  epy*c);
    u[1] = cmk(-emx*s,  emy*s);
    u[2] = cmk( emx*s,  emy*s);
    u[3] = cmk( epx*c, -epy*c);
}

__global__ __launch_bounds__(256)
void vqc_fused(const float* __restrict__ x, const float* __restrict__ W,
               const float* __restrict__ fcw, const float* __restrict__ fcb,
               float* __restrict__ out)
{
    __shared__ float PT[15][16];          // conj-PTMs: layers 1..3 x window pos 0..4
    __shared__ float bx[7][3], bz[7][3];  // layer-0 Bloch columns, wires i-3..i+3
    __shared__ float sC[256];             // compact tensor [b0*4+q1][lane=(q2,q3,b4)]
    __shared__ float sM[SPC][MST];        // per-sample Bloch vectors m[k][c] at k*3+c
    __shared__ __align__(16) float tF[4 * APAD];
    __shared__ int s_elect;

    const int i     = blockIdx.x;         // measured qubit
    const int chunk = blockIdx.y;         // 64-sample chunk
    const int tid   = threadIdx.x;
    const int lane  = tid & 31;
    const int wrp   = tid >> 5;
    const int sl    = tid >> 2;           // local sample 0..63
    const int as    = tid & 3;            // p0 slice in contraction
    const int b     = chunk * SPC + sl;

    // ---- prologue: column-parallel PTM + Bloch construction ----
    if (tid < 60) {
        int id = tid >> 2, p = tid & 3;
        int l = 1 + id / 5, a = id % 5;
        int w = i - 2 + a;
        float col[4];
        if (w >= 0 && w < NQ) {
            C2 u[4]; rot_u(W + (l*NQ + w)*3, u);
            ptm_col(u, p, col);
        } else {
            #pragma unroll
            for (int q = 0; q < 4; q++) col[q] = (q == p) ? 1.f : 0.f;
        }
        #pragma unroll
        for (int q = 0; q < 4; q++) PT[id][q*4 + p] = col[q];
    } else if (tid >= 64 && tid < 78) {
        int id = tid - 64;
        int k = id >> 1;
        int p = (id & 1) ? 3 : 1;
        int w = i - 3 + k;
        float col[4] = {0.f, 0.f, 0.f, 0.f};
        if (w >= 0 && w < NQ) {
            C2 u[4]; rot_u(W + w*3, u);
            C2 v[4] = { cmk(u[0].x,-u[0].y), cmk(u[2].x,-u[2].y),
                        cmk(u[1].x,-u[1].y), cmk(u[3].x,-u[3].y) };
            ptm_col(v, p, col);
        }
        float* dstv = (p == 1) ? bx[k] : bz[k];
        dstv[0] = col[1]; dstv[1] = col[2]; dstv[2] = col[3];
    }
    __syncthreads();                      // B1

    const int q2 = (lane >> 3) & 3, q3 = (lane >> 1) & 3, b4 = lane & 1;

    // ---- warp 0: tensor build -> compact sC (verified R11) ----
    if (wrp == 0) {
        const int ex1 = (i >= 1), ex2 = (i <= 14);
        const int zx1 = ex1 ? 3 : 0, zx2 = ex2 ? 3 : 0;
        const float cI = PT[12][3], cX = PT[12][7], cY = PT[12][11], cZ = PT[12][15];

        // Dense closed-form t64 (init has 4 nonzeros)
        const float* M6 = PT[6]; const float* M7 = PT[7]; const float* M8 = PT[8];
        float v0, v1;   // lane holds f=lane (v0), f=32+lane (v1); f = q1*16+q2*4+q3
        {
            int f0 = lane;
            int a1 = f0 >> 4, a2 = (f0 >> 2) & 3, a3 = f0 & 3;   // v1: a1+2
            float tIZ = cI*M7[a2*4+0] + cZ*M7[a2*4+3];
            float tXY = cX*M7[a2*4+1] + cY*M7[a2*4+2];
            float e80 = M8[a3*4+0], e8z = M8[a3*4+zx2];
            v0 = M6[a1*4+0]*e80*tIZ     + M6[a1*4+zx1]*e8z*tXY;
            v1 = M6[(a1+2)*4+0]*e80*tIZ + M6[(a1+2)*4+zx1]*e8z*tXY;
        }

        // D1 as a register GATHER (CZ label map is an involution)
        const int exA0 = (i >= 2), exA1 = (i >= 1), exA2 = (i <= 14), exA3 = (i <= 13);
        float Cg[8];
        {
            const bool need4 = (exA3 && ((q3 == 1) || (q3 == 2)));
            const bool ok4 = (b4 == (need4 ? 1 : 0));
            #pragma unroll
            for (int j = 0; j < 4; j++) {
                int p1 = j, p2 = q2, p3 = q3; float s = 1.f;
                if (exA1) {
                    bool xl = (p1==1)||(p1==2), xr = (p2==1)||(p2==2);
                    if (xl && xr && p1 != p2) s = -s;
                    int np1 = xr ? p1^3 : p1, np2 = xl ? p2^3 : p2;
                    p1 = np1; p2 = np2;
                }
                if (exA2) {
                    bool xl = (p2==1)||(p2==2), xr = (p3==1)||(p3==2);
                    if (xl && xr && p2 != p3) s = -s;
                    int np2 = xr ? p2^3 : p2, np3 = xl ? p3^3 : p3;
                    p2 = np2; p3 = np3;
                }
                int fsrc = p1*16 + p2*4 + p3;
                float a0 = __shfl_sync(0xffffffffu, v0, fsrc & 31);
                float a1 = __shfl_sync(0xffffffffu, v1, fsrc & 31);
                float val = s * ((fsrc & 32) ? a1 : a0);
                bool need0 = (exA0 && ((p1 == 1) || (p1 == 2)));
                Cg[j]     = (ok4 && !need0) ? val : 0.f;
                Cg[j + 4] = (ok4 &&  need0) ? val : 0.f;
            }
        }
        {   // layer-1 axis q1 (PT[1]) : register 4x4 within each b0 group
            const float* M = PT[1];
            float N[8];
            #pragma unroll
            for (int g0 = 0; g0 < 2; g0++)
                #pragma unroll
                for (int q = 0; q < 4; q++)
                    N[g0*4+q] = M[q*4+0]*Cg[g0*4+0] + M[q*4+1]*Cg[g0*4+1]
                              + M[q*4+2]*Cg[g0*4+2] + M[q*4+3]*Cg[g0*4+3];
            #pragma unroll
            for (int k = 0; k < 8; k++) Cg[k] = N[k];
        }
        {   // layer-1 axis q2 (PT[2]) : shfl_xor 8,16,24
            const float* M = PT[2];
            float n[8];
            #pragma unroll
            for (int k = 0; k < 8; k++) {
                float s1 = __shfl_xor_sync(0xffffffffu, Cg[k], 8);
                float s2 = __shfl_xor_sync(0xffffffffu, Cg[k], 16);
                float s3 = __shfl_xor_sync(0xffffffffu, Cg[k], 24);
                n[k] = M[q2*4+q2]*Cg[k] + M[q2*4+(q2^1)]*s1
                     + M[q2*4+(q2^2)]*s2 + M[q2*4+(q2^3)]*s3;
            }
            #pragma unroll
            for (int k = 0; k < 8; k++) Cg[k] = n[k];
        }
        {   // layer-1 axis q3 (PT[3]) : shfl_xor 2,4,6
            const float* M = PT[3];
            float n[8];
            #pragma unroll
            for (int k = 0; k < 8; k++) {
                float s1 = __shfl_xor_sync(0xffffffffu, Cg[k], 2);
                float s2 = __shfl_xor_sync(0xffffffffu, Cg[k], 4);
                float s3 = __shfl_xor_sync(0xffffffffu, Cg[k], 6);
                n[k] = M[q3*4+q3]*Cg[k] + M[q3*4+(q3^1)]*s1
                     + M[q3*4+(q3^2)]*s2 + M[q3*4+(q3^3)]*s3;
            }
            #pragma unroll
            for (int k = 0; k < 8; k++) Cg[k] = n[k];
        }
        #pragma unroll
        for (int k = 0; k < 8; k++) sC[k*32 + lane] = Cg[k];
    } else {
        // ---- warps 1-7: dedup Bloch vectors, one (sample, wire) pair each ----
        int pid = tid - 32;               // 0..223; pairs pid and pid+224 (448 total)
        #pragma unroll
        for (int r = 0; r < 2; r++) {
            int p = pid + r * 224;
            int s2 = p / 7, k = p % 7;
            int w = i - 3 + k;
            float xval = (w >= 0 && w < NQ) ? x[(chunk*SPC + s2)*NQ + w] : 0.f;
            float sx, cx; __sincosf(xval, &sx, &cx);   // RY(x)|0> Bloch=(sx,0,cx)
            sM[s2][k*3+0] = sx*bx[k][0] + cx*bz[k][0];
            sM[s2][k*3+1] = sx*bx[k][1] + cx*bz[k][1];
            sM[s2][k*3+2] = sx*bx[k][2] + cx*bz[k][2];
        }
    }
    __syncthreads();                      // B2: sC + sM published

    // ---- edge expansion (PTM cols I,Z) + D0 CZ scatter; all 8 warps ----
    {
        const int p0 = wrp >> 1;
        const float c00 = PT[0][p0*4], c0z = PT[0][p0*4+3];
        const int p4 = ((wrp & 1) << 1) | b4;
        const float* M4 = PT[4];
        const int le = lane & ~1, lo = lane | 1;
        #pragma unroll
        for (int r = 0; r < 4; r++) {
            float h0 = c00 * sC[r*32 + le] + c0z * sC[(4+r)*32 + le];  // b4=0
            float h1 = c00 * sC[r*32 + lo] + c0z * sC[(4+r)*32 + lo];  // b4=1
            float sg = M4[p4*4+0]*h0 + M4[p4*4+3]*h1;
            int p[5] = { p0, r, q2, q3, p4 };
            #pragma unroll
            for (int a = 0; a < 4; a++) {
                int wl = i - 2 + a;
                if (wl >= 0 && wl + 1 < NQ) {
                    int pa = p[a], pb = p[a+1];
                    bool xl = (pa==1)||(pa==2), xr = (pb==1)||(pb==2);
                    if (xl && xr && pa != pb) sg = -sg;
                    if (xr) p[a]   = pa ^ 3;
                    if (xl) p[a+1] = pb ^ 3;
                }
            }
            tF[p[0]*APAD + (p[1]<<6) + (p[2]<<4) + (p[3]<<2) + p[4]] = sg;
        }
    }

    // contraction vectors from deduped Bloch smem (ready at B2)
    const float* ms = sM[sl];
    float dL = (i - 3 >= 0) ? ms[2]  : 1.f;
    float dR = (i + 3 < NQ) ? ms[20] : 1.f;
    float v0c[4], v1c[4], v2c[4], v3c[4], v4c[4];
    v0c[0]=1.f; v0c[1]=dL*ms[3];  v0c[2]=dL*ms[4];  v0c[3]=ms[5];
    v1c[0]=1.f; v1c[1]=ms[6];     v1c[2]=ms[7];     v1c[3]=ms[8];
    v2c[0]=1.f; v2c[1]=ms[9];     v2c[2]=ms[10];    v2c[3]=ms[11];
    v3c[0]=1.f; v3c[1]=ms[12];    v3c[2]=ms[13];    v3c[3]=ms[14];
    v4c[0]=1.f; v4c[1]=dR*ms[15]; v4c[2]=dR*ms[16]; v4c[3]=ms[17];
    __syncthreads();                      // B3

    // ---- per-sample contraction: 4 threads/sample (p0 slice = as) ----
    const float4* Ta = reinterpret_cast<const float4*>(tF + as * APAD);
    float sb[4];
    #pragma unroll
    for (int q = 0; q < 4; q++) {
        float acc = 0.f;
        #pragma unroll
        for (int c = 0; c < 4; c++) {
            float sc = 0.f;
            #pragma unroll
            for (int d = 0; d < 4; d++) {
                float4 t4 = Ta[q*16 + c*4 + d];
                sc += v3c[d] * (t4.x*v4c[0] + t4.y*v4c[1] + t4.z*v4c[2] + t4.w*v4c[3]);
            }
            acc += v2c[c] * sc;
        }
        sb[q] = acc;
    }
    float z = v0c[as] * (v1c[0]*sb[0] + v1c[1]*sb[1] + v1c[2]*sb[2] + v1c[3]*sb[3]);
    z += __shfl_xor_sync(0xffffffffu, z, 1);
    z += __shfl_xor_sync(0xffffffffu, z, 2);
    if (as == 0) g_z[b * NQ + i] = z;

    // ---- fused FC head: last CTA of this chunk, register-only GEMV ----
    __syncthreads();                      // B4
    if (tid == 0) {
        __threadfence();
        int old = atomicAdd(&g_cnt[chunk], 1);
        int e = (old == NQ - 1);
        if (e) {
            __threadfence();
            atomicExch(&g_cnt[chunk], 0);   // reset for next graph replay
        }
        s_elect = e;
    }
    __syncthreads();                      // B5
    if (s_elect) {
        // thread -> (sample sl, quarter as); one float4 of z per thread
        const float4 zz = __ldcg(reinterpret_cast<const float4*>(
                              g_z + (chunk * SPC + sl) * NQ) + as);
        float pa[NA];
        #pragma unroll
        for (int a = 0; a < NA; a++) {
            const float4 wv = *reinterpret_cast<const float4*>(fcw + a*NQ + as*4);
            pa[a] = zz.x*wv.x + zz.y*wv.y + zz.z*wv.z + zz.w*wv.w;
        }
        #pragma unroll
        for (int a = 0; a < NA; a++) {
            pa[a] += __shfl_xor_sync(0xffffffffu, pa[a], 1);
            pa[a] += __shfl_xor_sync(0xffffffffu, pa[a], 2);
        }
        if (as == 0) {
            #pragma unroll
            for (int a = 0; a < NA; a++)
                out[(chunk * SPC + sl) * NA + a] = pa[a] + fcb[a];
        }
    }
}

extern "C" void kernel_launch(void* const* d_in, const int* in_sizes, int n_in,
                              void* d_out, int out_size) {
    const float* x   = (const float*)d_in[0];   // [512,16]
    const float* W   = (const float*)d_in[1];   // [4,16,3]
    const float* fcw = (const float*)d_in[2];   // [6,16]
    const float* fcb = (const float*)d_in[3];   // [6]
    float* out = (float*)d_out;                 // [512,6]
    (void)in_sizes; (void)n_in; (void)out_size;
    dim3 grid(NQ, NCHUNK);
    vqc_fused<<<grid, 256>>>(x, W, fcw, fcb, out);
}

// round 13
// speedup vs baseline: 1.2007x; 1.1075x over previous
#include <cuda_runtime.h>
#include <math.h>

// PennyLaneBasicDQN: 16-qubit VQC (RY embed + 4x[Rot,CZ chain]) + linear head.
// Heisenberg light-cone + Pauli-transfer-matrix method (verified R3..R12).
// R13: latency-hiding round — (a) x prefetched at kernel entry (R12 had moved
// it onto the post-B1 chain), (b) fcw/fcb prefetched before the elect atomic,
// (c) counter reset moved off the elect critical path.

#define NQ 16
#define NA 6
#define BATCHSZ 512
#define NCHUNK 8
#define SPC 64
#define APAD 264          // padded p0-slice stride (floats)
#define MST 22            // sM row stride (floats)

__device__ __align__(16) float g_z[BATCHSZ * NQ];
__device__ int   g_cnt[NCHUNK] = {0};

struct C2 { float x, y; };
__device__ __forceinline__ C2 cmk(float a, float b){ C2 r; r.x=a; r.y=b; return r; }
__device__ __forceinline__ C2 cml(C2 a, C2 b){ return cmk(a.x*b.x - a.y*b.y, a.x*b.y + a.y*b.x); }
__device__ __forceinline__ C2 cad(C2 a, C2 b){ return cmk(a.x+b.x, a.y+b.y); }

// Column p of the 4x4 real PTM of conjugation O -> U^dag O U
__device__ __forceinline__ void ptm_col(const C2 u[4], int p, float col[4]) {
    C2 ud00 = cmk(u[0].x, -u[0].y), ud01 = cmk(u[2].x, -u[2].y);
    C2 ud10 = cmk(u[1].x, -u[1].y), ud11 = cmk(u[3].x, -u[3].y);
    C2 s00, s01, s10, s11;                 // sigma_p * U
    if (p == 0)      { s00=u[0]; s01=u[1]; s10=u[2]; s11=u[3]; }
    else if (p == 1) { s00=u[2]; s01=u[3]; s10=u[0]; s11=u[1]; }
    else if (p == 2) {
        s00 = cmk( u[2].y, -u[2].x);
        s01 = cmk( u[3].y, -u[3].x);
        s10 = cmk(-u[0].y,  u[0].x);
        s11 = cmk(-u[1].y,  u[1].x);
    } else           { s00=u[0]; s01=u[1]; s10=cmk(-u[2].x,-u[2].y); s11=cmk(-u[3].x,-u[3].y); }
    C2 A00 = cad(cml(ud00, s00), cml(ud01, s10));
    C2 A01 = cad(cml(ud00, s01), cml(ud01, s11));
    C2 A10 = cad(cml(ud10, s00), cml(ud11, s10));
    C2 A11 = cad(cml(ud10, s01), cml(ud11, s11));
    col[0] = 0.5f*(A00.x + A11.x);
    col[1] = 0.5f*(A01.x + A10.x);
    col[2] = 0.5f*(A10.y - A01.y);
    col[3] = 0.5f*(A00.x - A11.x);
}

// PennyLane Rot(phi,theta,omega) = RZ(omega) RY(theta) RZ(phi)
__device__ __forceinline__ void rot_u(const float* wp, C2 u[4]) {
    float phi = wp[0], th = wp[1], om = wp[2];
    float c, s; __sincosf(0.5f*th, &s, &c);
    float epx, epy, emx, emy;
    __sincosf(-0.5f*(phi+om), &epy, &epx);
    __sincosf(-0.5f*(phi-om), &emy, &emx);
    u[0] = cmk( epx*c,  epy*c);
    u[1] = cmk(-emx*s,  emy*s);
    u[2] = cmk( emx*s,  emy*s);
    u[3] = cmk( epx*c, -epy*c);
}

__global__ __launch_bounds__(256)
void vqc_fused(const float* __restrict__ x, const float* __restrict__ W,
               const float* __restrict__ fcw, const float* __restrict__ fcb,
               float* __restrict__ out)
{
    __shared__ float PT[15][16];          // conj-PTMs: layers 1..3 x window pos 0..4
    __shared__ float bx[7][3], bz[7][3];  // layer-0 Bloch columns, wires i-3..i+3
    __shared__ float sC[256];             // compact tensor [b0*4+q1][lane=(q2,q3,b4)]
    __shared__ float sM[SPC][MST];        // per-sample Bloch vectors m[k][c] at k*3+c
    __shared__ __align__(16) float tF[4 * APAD];
    __shared__ int s_elect;

    const int i     = blockIdx.x;         // measured qubit
    const int chunk = blockIdx.y;         // 64-sample chunk
    const int tid   = threadIdx.x;
    const int lane  = tid & 31;
    const int wrp   = tid >> 5;
    const int sl    = tid >> 2;           // local sample 0..63
    const int as    = tid & 3;            // p0 slice in contraction
    const int b     = chunk * SPC + sl;

    // ---- prefetch x at kernel entry (producer warps 1-7; latency hidden
    //      behind the prologue + B1) ----
    float xpre[2];
    int s2a[2], ka[2];
    if (wrp > 0) {
        int pid = tid - 32;               // 0..223
        #pragma unroll
        for (int r = 0; r < 2; r++) {
            int p = pid + r * 224;
            s2a[r] = p / 7; ka[r] = p % 7;
            int w = i - 3 + ka[r];
            xpre[r] = (w >= 0 && w < NQ) ? x[(chunk*SPC + s2a[r])*NQ + w] : 0.f;
        }
    }

    // ---- prologue: column-parallel PTM + Bloch construction ----
    if (tid < 60) {
        int id = tid >> 2, p = tid & 3;
        int l = 1 + id / 5, a = id % 5;
        int w = i - 2 + a;
        float col[4];
        if (w >= 0 && w < NQ) {
            C2 u[4]; rot_u(W + (l*NQ + w)*3, u);
            ptm_col(u, p, col);
        } else {
            #pragma unroll
            for (int q = 0; q < 4; q++) col[q] = (q == p) ? 1.f : 0.f;
        }
        #pragma unroll
        for (int q = 0; q < 4; q++) PT[id][q*4 + p] = col[q];
    } else if (tid >= 64 && tid < 78) {
        int id = tid - 64;
        int k = id >> 1;
        int p = (id & 1) ? 3 : 1;
        int w = i - 3 + k;
        float col[4] = {0.f, 0.f, 0.f, 0.f};
        if (w >= 0 && w < NQ) {
            C2 u[4]; rot_u(W + w*3, u);
            C2 v[4] = { cmk(u[0].x,-u[0].y), cmk(u[2].x,-u[2].y),
                        cmk(u[1].x,-u[1].y), cmk(u[3].x,-u[3].y) };
            ptm_col(v, p, col);
        }
        float* dstv = (p == 1) ? bx[k] : bz[k];
        dstv[0] = col[1]; dstv[1] = col[2]; dstv[2] = col[3];
    }
    __syncthreads();                      // B1

    const int q2 = (lane >> 3) & 3, q3 = (lane >> 1) & 3, b4 = lane & 1;

    // ---- warp 0: tensor build -> compact sC (verified R11) ----
    if (wrp == 0) {
        const int ex1 = (i >= 1), ex2 = (i <= 14);
        const int zx1 = ex1 ? 3 : 0, zx2 = ex2 ? 3 : 0;
        const float cI = PT[12][3], cX = PT[12][7], cY = PT[12][11], cZ = PT[12][15];

        // Dense closed-form t64 (init has 4 nonzeros)
        const float* M6 = PT[6]; const float* M7 = PT[7]; const float* M8 = PT[8];
        float v0, v1;   // lane holds f=lane (v0), f=32+lane (v1); f = q1*16+q2*4+q3
        {
            int f0 = lane;
            int a1 = f0 >> 4, a2 = (f0 >> 2) & 3, a3 = f0 & 3;   // v1: a1+2
            float tIZ = cI*M7[a2*4+0] + cZ*M7[a2*4+3];
            float tXY = cX*M7[a2*4+1] + cY*M7[a2*4+2];
            float e80 = M8[a3*4+0], e8z = M8[a3*4+zx2];
            v0 = M6[a1*4+0]*e80*tIZ     + M6[a1*4+zx1]*e8z*tXY;
            v1 = M6[(a1+2)*4+0]*e80*tIZ + M6[(a1+2)*4+zx1]*e8z*tXY;
        }

        // D1 as a register GATHER (CZ label map is an involution)
        const int exA0 = (i >= 2), exA1 = (i >= 1), exA2 = (i <= 14), exA3 = (i <= 13);
        float Cg[8];
        {
            const bool need4 = (exA3 && ((q3 == 1) || (q3 == 2)));
            const bool ok4 = (b4 == (need4 ? 1 : 0));
            #pragma unroll
            for (int j = 0; j < 4; j++) {
                int p1 = j, p2 = q2, p3 = q3; float s = 1.f;
                if (exA1) {
                    bool xl = (p1==1)||(p1==2), xr = (p2==1)||(p2==2);
                    if (xl && xr && p1 != p2) s = -s;
                    int np1 = xr ? p1^3 : p1, np2 = xl ? p2^3 : p2;
                    p1 = np1; p2 = np2;
                }
                if (exA2) {
                    bool xl = (p2==1)||(p2==2), xr = (p3==1)||(p3==2);
                    if (xl && xr && p2 != p3) s = -s;
                    int np2 = xr ? p2^3 : p2, np3 = xl ? p3^3 : p3;
                    p2 = np2; p3 = np3;
                }
                int fsrc = p1*16 + p2*4 + p3;
                float a0 = __shfl_sync(0xffffffffu, v0, fsrc & 31);
                float a1 = __shfl_sync(0xffffffffu, v1, fsrc & 31);
                float val = s * ((fsrc & 32) ? a1 : a0);
                bool need0 = (exA0 && ((p1 == 1) || (p1 == 2)));
                Cg[j]     = (ok4 && !need0) ? val : 0.f;
                Cg[j + 4] = (ok4 &&  need0) ? val : 0.f;
            }
        }
        {   // layer-1 axis q1 (PT[1]) : register 4x4 within each b0 group
            const float* M = PT[1];
            float N[8];
            #pragma unroll
            for (int g0 = 0; g0 < 2; g0++)
                #pragma unroll
                for (int q = 0; q < 4; q++)
                    N[g0*4+q] = M[q*4+0]*Cg[g0*4+0] + M[q*4+1]*Cg[g0*4+1]
                              + M[q*4+2]*Cg[g0*4+2] + M[q*4+3]*Cg[g0*4+3];
            #pragma unroll
            for (int k = 0; k < 8; k++) Cg[k] = N[k];
        }
        {   // layer-1 axis q2 (PT[2]) : shfl_xor 8,16,24
            const float* M = PT[2];
            float n[8];
            #pragma unroll
            for (int k = 0; k < 8; k++) {
                float s1 = __shfl_xor_sync(0xffffffffu, Cg[k], 8);
                float s2 = __shfl_xor_sync(0xffffffffu, Cg[k], 16);
                float s3 = __shfl_xor_sync(0xffffffffu, Cg[k], 24);
                n[k] = M[q2*4+q2]*Cg[k] + M[q2*4+(q2^1)]*s1
                     + M[q2*4+(q2^2)]*s2 + M[q2*4+(q2^3)]*s3;
            }
            #pragma unroll
            for (int k = 0; k < 8; k++) Cg[k] = n[k];
        }
        {   // layer-1 axis q3 (PT[3]) : shfl_xor 2,4,6
            const float* M = PT[3];
            float n[8];
            #pragma unroll
            for (int k = 0; k < 8; k++) {
                float s1 = __shfl_xor_sync(0xffffffffu, Cg[k], 2);
                float s2 = __shfl_xor_sync(0xffffffffu, Cg[k], 4);
                float s3 = __shfl_xor_sync(0xffffffffu, Cg[k], 6);
                n[k] = M[q3*4+q3]*Cg[k] + M[q3*4+(q3^1)]*s1
                     + M[q3*4+(q3^2)]*s2 + M[q3*4+(q3^3)]*s3;
            }
            #pragma unroll
            for (int k = 0; k < 8; k++) Cg[k] = n[k];
        }
        #pragma unroll
        for (int k = 0; k < 8; k++) sC[k*32 + lane] = Cg[k];
    } else {
        // ---- warps 1-7: dedup Bloch vectors (x already in registers) ----
        #pragma unroll
        for (int r = 0; r < 2; r++) {
            int s2 = s2a[r], k = ka[r];
            float sx, cx; __sincosf(xpre[r], &sx, &cx);   // RY(x)|0> Bloch=(sx,0,cx)
            sM[s2][k*3+0] = sx*bx[k][0] + cx*bz[k][0];
            sM[s2][k*3+1] = sx*bx[k][1] + cx*bz[k][1];
            sM[s2][k*3+2] = sx*bx[k][2] + cx*bz[k][2];
        }
    }
    __syncthreads();                      // B2: sC + sM published

    // ---- edge expansion (PTM cols I,Z) + D0 CZ scatter; all 8 warps ----
    {
        const int p0 = wrp >> 1;
        const float c00 = PT[0][p0*4], c0z = PT[0][p0*4+3];
        const int p4 = ((wrp & 1) << 1) | b4;
        const float* M4 = PT[4];
        const int le = lane & ~1, lo = lane | 1;
        #pragma unroll
        for (int r = 0; r < 4; r++) {
            float h0 = c00 * sC[r*32 + le] + c0z * sC[(4+r)*32 + le];  // b4=0
            float h1 = c00 * sC[r*32 + lo] + c0z * sC[(4+r)*32 + lo];  // b4=1
            float sg = M4[p4*4+0]*h0 + M4[p4*4+3]*h1;
            int p[5] = { p0, r, q2, q3, p4 };
            #pragma unroll
            for (int a = 0; a < 4; a++) {
                int wl = i - 2 + a;
                if (wl >= 0 && wl + 1 < NQ) {
                    int pa = p[a], pb = p[a+1];
                    bool xl = (pa==1)||(pa==2), xr = (pb==1)||(pb==2);
                    if (xl && xr && pa != pb) sg = -sg;
                    if (xr) p[a]   = pa ^ 3;
                    if (xl) p[a+1] = pb ^ 3;
                }
            }
            tF[p[0]*APAD + (p[1]<<6) + (p[2]<<4) + (p[3]<<2) + p[4]] = sg;
        }
    }

    // contraction vectors from deduped Bloch smem (ready at B2)
    const float* ms = sM[sl];
    float dL = (i - 3 >= 0) ? ms[2]  : 1.f;
    float dR = (i + 3 < NQ) ? ms[20] : 1.f;
    float v0c[4], v1c[4], v2c[4], v3c[4], v4c[4];
    v0c[0]=1.f; v0c[1]=dL*ms[3];  v0c[2]=dL*ms[4];  v0c[3]=ms[5];
    v1c[0]=1.f; v1c[1]=ms[6];     v1c[2]=ms[7];     v1c[3]=ms[8];
    v2c[0]=1.f; v2c[1]=ms[9];     v2c[2]=ms[10];    v2c[3]=ms[11];
    v3c[0]=1.f; v3c[1]=ms[12];    v3c[2]=ms[13];    v3c[3]=ms[14];
    v4c[0]=1.f; v4c[1]=dR*ms[15]; v4c[2]=dR*ms[16]; v4c[3]=ms[17];
    __syncthreads();                      // B3

    // ---- per-sample contraction: 4 threads/sample (p0 slice = as) ----
    const float4* Ta = reinterpret_cast<const float4*>(tF + as * APAD);
    float sb[4];
    #pragma unroll
    for (int q = 0; q < 4; q++) {
        float acc = 0.f;
        #pragma unroll
        for (int c = 0; c < 4; c++) {
            float sc = 0.f;
            #pragma unroll
            for (int d = 0; d < 4; d++) {
                float4 t4 = Ta[q*16 + c*4 + d];
                sc += v3c[d] * (t4.x*v4c[0] + t4.y*v4c[1] + t4.z*v4c[2] + t4.w*v4c[3]);
            }
            acc += v2c[c] * sc;
        }
        sb[q] = acc;
    }
    float z = v0c[as] * (v1c[0]*sb[0] + v1c[1]*sb[1] + v1c[2]*sb[2] + v1c[3]*sb[3]);
    z += __shfl_xor_sync(0xffffffffu, z, 1);
    z += __shfl_xor_sync(0xffffffffu, z, 2);
    if (as == 0) g_z[b * NQ + i] = z;

    // ---- prefetch FC weights (all CTAs; hides L2 latency behind elect sync) ----
    float4 wv[NA];
    float fcbv[NA];
    #pragma unroll
    for (int a = 0; a < NA; a++) {
        wv[a] = *reinterpret_cast<const float4*>(fcw + a*NQ + as*4);
        fcbv[a] = fcb[a];
    }

    // ---- fused FC head: last CTA of this chunk, register-only GEMV ----
    __syncthreads();                      // B4
    if (tid == 0) {
        __threadfence();
        int old = atomicAdd(&g_cnt[chunk], 1);
        int e = (old == NQ - 1);
        s_elect = e;
        if (e) atomicExch(&g_cnt[chunk], 0);   // reset for next replay (off-path)
    }
    __syncthreads();                      // B5
    if (s_elect) {
        // thread -> (sample sl, quarter as); one float4 of z per thread
        const float4 zz = __ldcg(reinterpret_cast<const float4*>(
                              g_z + (chunk * SPC + sl) * NQ) + as);
        float pa[NA];
        #pragma unroll
        for (int a = 0; a < NA; a++)
            pa[a] = zz.x*wv[a].x + zz.y*wv[a].y + zz.z*wv[a].z + zz.w*wv[a].w;
        #pragma unroll
        for (int a = 0; a < NA; a++) {
            pa[a] += __shfl_xor_sync(0xffffffffu, pa[a], 1);
            pa[a] += __shfl_xor_sync(0xffffffffu, pa[a], 2);
        }
        if (as == 0) {
            #pragma unroll
            for (int a = 0; a < NA; a++)
                out[(chunk * SPC + sl) * NA + a] = pa[a] + fcbv[a];
        }
    }
}

extern "C" void kernel_launch(void* const* d_in, const int* in_sizes, int n_in,
                              void* d_out, int out_size) {
    const float* x   = (const float*)d_in[0];   // [512,16]
    const float* W   = (const float*)d_in[1];   // [4,16,3]
    const float* fcw = (const float*)d_in[2];   // [6,16]
    const float* fcb = (const float*)d_in[3];   // [6]
    float* out = (float*)d_out;                 // [512,6]
    (void)in_sizes; (void)n_in; (void)out_size;
    dim3 grid(NQ, NCHUNK);
    vqc_fused<<<grid, 256>>>(x, W, fcw, fcb, out);
}